// round 3
// baseline (speedup 1.0000x reference)
#include <cuda_runtime.h>
#include <cuda_bf16.h>

// ---------------------------------------------------------------------------
// QuantWeightNet: out = sigmoid(relu(relu(relu(x@W1q.T+b1)@W2q.T+b2)@W4q.T+b4)@W3q.T)*0.8+0.1
// W*q = per-tensor symmetric 3-bit quant: s = max|W|/3; q = clip(rint(W/s),-3,3)*s
//
// Strategy:
//   prep kernel (1 block): compute scales + quantized weights, store as
//   duplicate-packed f32x2 (w,w) in __device__ buffer.
//   main kernel: 2 rows per thread via packed fma.rn.f32x2; weights in shared;
//   streaming cache hints on the once-touched x/out; scalar tail for odd B.
// ---------------------------------------------------------------------------

#define N_FEAT 64

// packed-weight buffer layout (ull = one f32x2 duplicated weight)
#define OFF_W1 0        // [7][64]   448
#define OFF_W2 448      // [20][8]   160 (j padded 7->8 with 0)
#define OFF_W4 608      // [20][20]  400
#define OFF_W3 1008     // [20]      20
#define OFF_B1 1028     // 7
#define OFF_B2 1035     // 20
#define OFF_B4 1055     // 20
#define NW_PAD 1076     // even

__device__ unsigned long long g_w[NW_PAD];

// ---- f32x2 helpers ----
__device__ __forceinline__ unsigned long long pk2(float lo, float hi) {
    unsigned long long r;
    asm("mov.b64 %0, {%1, %2};" : "=l"(r) : "f"(lo), "f"(hi));
    return r;
}
__device__ __forceinline__ void upk2(unsigned long long v, float& lo, float& hi) {
    asm("mov.b64 {%0, %1}, %2;" : "=f"(lo), "=f"(hi) : "l"(v));
}
__device__ __forceinline__ unsigned long long ffma2(unsigned long long a,
                                                    unsigned long long b,
                                                    unsigned long long c) {
    unsigned long long d;
    asm("fma.rn.f32x2 %0, %1, %2, %3;" : "=l"(d) : "l"(a), "l"(b), "l"(c));
    return d;
}
__device__ __forceinline__ unsigned long long relu2(unsigned long long v) {
    float lo, hi;
    upk2(v, lo, hi);
    return pk2(fmaxf(lo, 0.0f), fmaxf(hi, 0.0f));
}

// ---- prep: quantize weights once per launch ----
__device__ __forceinline__ float block_maxabs(const float* w, int n, float* red, int t) {
    float m = 0.0f;
    for (int i = t; i < n; i += 256) m = fmaxf(m, fabsf(w[i]));
    red[t] = m;
    __syncthreads();
    for (int s = 128; s > 0; s >>= 1) {
        if (t < s) red[t] = fmaxf(red[t], red[t + s]);
        __syncthreads();
    }
    float r = red[0];
    __syncthreads();
    return r;
}
__device__ __forceinline__ float qv(float w, float s) {
    float q = rintf(w / s);             // round-half-even, matches jnp.round
    q = fminf(fmaxf(q, -3.0f), 3.0f);
    return q * s;
}

__global__ void prep_kernel(const float* __restrict__ W1, const float* __restrict__ b1,
                            const float* __restrict__ W2, const float* __restrict__ b2,
                            const float* __restrict__ W4, const float* __restrict__ b4,
                            const float* __restrict__ W3) {
    __shared__ float red[256];
    int t = threadIdx.x;
    float s1 = block_maxabs(W1, 7 * 64, red, t)  * (1.0f / 3.0f);
    float s2 = block_maxabs(W2, 20 * 7, red, t)  * (1.0f / 3.0f);
    float s4 = block_maxabs(W4, 20 * 20, red, t) * (1.0f / 3.0f);
    float s3 = block_maxabs(W3, 20, red, t)      * (1.0f / 3.0f);

    for (int i = t; i < 448; i += 256) {
        float v = qv(W1[i], s1);
        g_w[OFF_W1 + i] = pk2(v, v);
    }
    for (int i = t; i < 160; i += 256) {   // W2 padded [20][8]
        int r = i >> 3, c = i & 7;
        float v = (c < 7) ? qv(W2[r * 7 + c], s2) : 0.0f;
        g_w[OFF_W2 + i] = pk2(v, v);
    }
    for (int i = t; i < 400; i += 256) {
        float v = qv(W4[i], s4);
        g_w[OFF_W4 + i] = pk2(v, v);
    }
    for (int i = t; i < 20; i += 256) {
        float v = qv(W3[i], s3);
        g_w[OFF_W3 + i] = pk2(v, v);
    }
    for (int i = t; i < 7; i += 256)  g_w[OFF_B1 + i] = pk2(b1[i], b1[i]);
    for (int i = t; i < 20; i += 256) g_w[OFF_B2 + i] = pk2(b2[i], b2[i]);
    for (int i = t; i < 20; i += 256) g_w[OFF_B4 + i] = pk2(b4[i], b4[i]);
}

// ---- shared forward path on packed pairs; duplicate lane B for tail rows ----
__device__ __forceinline__ float2 forward_pair(const unsigned long long* __restrict__ sw,
                                               const float4* __restrict__ xA,
                                               const float4* __restrict__ xB) {
    // fc1: 64 -> 7
    unsigned long long acc1[7];
#pragma unroll
    for (int j = 0; j < 7; j++) acc1[j] = sw[OFF_B1 + j];

#pragma unroll
    for (int c = 0; c < 16; c++) {
        float4 a = __ldcs(&xA[c]);     // streaming: touched exactly once
        float4 b = __ldcs(&xB[c]);
        unsigned long long p0 = pk2(a.x, b.x);
        unsigned long long p1 = pk2(a.y, b.y);
        unsigned long long p2 = pk2(a.z, b.z);
        unsigned long long p3 = pk2(a.w, b.w);
#pragma unroll
        for (int j = 0; j < 7; j++) {
            ulonglong2 w01 = *reinterpret_cast<const ulonglong2*>(&sw[OFF_W1 + j * 64 + 4 * c]);
            ulonglong2 w23 = *reinterpret_cast<const ulonglong2*>(&sw[OFF_W1 + j * 64 + 4 * c + 2]);
            acc1[j] = ffma2(p0, w01.x, acc1[j]);
            acc1[j] = ffma2(p1, w01.y, acc1[j]);
            acc1[j] = ffma2(p2, w23.x, acc1[j]);
            acc1[j] = ffma2(p3, w23.y, acc1[j]);
        }
    }

    unsigned long long h1[8];
#pragma unroll
    for (int j = 0; j < 7; j++) h1[j] = relu2(acc1[j]);
    h1[7] = 0ULL;

    // fc2: 7 -> 20 (padded to 8)
    unsigned long long h2[20];
#pragma unroll
    for (int i = 0; i < 20; i++) {
        unsigned long long acc = sw[OFF_B2 + i];
#pragma unroll
        for (int jj = 0; jj < 4; jj++) {
            ulonglong2 w = *reinterpret_cast<const ulonglong2*>(&sw[OFF_W2 + i * 8 + 2 * jj]);
            acc = ffma2(h1[2 * jj], w.x, acc);
            acc = ffma2(h1[2 * jj + 1], w.y, acc);
        }
        h2[i] = relu2(acc);
    }

    // fc4: 20 -> 20
    unsigned long long h3[20];
#pragma unroll
    for (int i = 0; i < 20; i++) {
        unsigned long long acc = sw[OFF_B4 + i];
#pragma unroll
        for (int jj = 0; jj < 10; jj++) {
            ulonglong2 w = *reinterpret_cast<const ulonglong2*>(&sw[OFF_W4 + i * 20 + 2 * jj]);
            acc = ffma2(h2[2 * jj], w.x, acc);
            acc = ffma2(h2[2 * jj + 1], w.y, acc);
        }
        h3[i] = relu2(acc);
    }

    // fc3: 20 -> 1, sigmoid*0.8+0.1
    unsigned long long acc = 0ULL;
#pragma unroll
    for (int jj = 0; jj < 10; jj++) {
        ulonglong2 w = *reinterpret_cast<const ulonglong2*>(&sw[OFF_W3 + 2 * jj]);
        acc = ffma2(h3[2 * jj], w.x, acc);
        acc = ffma2(h3[2 * jj + 1], w.y, acc);
    }
    float zA, zB;
    upk2(acc, zA, zB);
    float oA = 0.8f / (1.0f + __expf(-zA)) + 0.1f;
    float oB = 0.8f / (1.0f + __expf(-zB)) + 0.1f;
    return make_float2(oA, oB);
}

// ---- main: 2 rows per thread, packed f32x2 math ----
__global__ __launch_bounds__(256, 2)
void mlp_kernel(const float* __restrict__ x, float* __restrict__ out,
                int nPairs, int nRows) {
    __shared__ __align__(16) unsigned long long sw[NW_PAD];
    for (int i = threadIdx.x; i < NW_PAD; i += 256) sw[i] = g_w[i];
    __syncthreads();

    long long gtid = (long long)blockIdx.x * 256 + threadIdx.x;
    if (gtid >= nPairs) return;
    long long row0 = gtid * 2;

    const float4* xA = reinterpret_cast<const float4*>(x + row0 * N_FEAT);

    if (row0 + 1 < nRows) {
        float2 o = forward_pair(sw, xA, xA + (N_FEAT / 4));
        __stcs(reinterpret_cast<float2*>(out + row0), o);
    } else {
        // odd tail: duplicate the single row into both lanes, write lane A
        float2 o = forward_pair(sw, xA, xA);
        out[row0] = o.x;
    }
}

extern "C" void kernel_launch(void* const* d_in, const int* in_sizes, int n_in,
                              void* d_out, int out_size) {
    const float* x  = (const float*)d_in[0];
    const float* W1 = (const float*)d_in[1];
    const float* b1 = (const float*)d_in[2];
    const float* W2 = (const float*)d_in[3];
    const float* b2 = (const float*)d_in[4];
    const float* W4 = (const float*)d_in[5];
    const float* b4 = (const float*)d_in[6];
    const float* W3 = (const float*)d_in[7];
    float* out = (float*)d_out;

    int B = in_sizes[0] / N_FEAT;     // 4,000,000
    int nPairs = (B + 1) / 2;
    int grid = (nPairs + 255) / 256;

    prep_kernel<<<1, 256>>>(W1, b1, W2, b2, W4, b4, W3);
    mlp_kernel<<<grid, 256>>>(x, out, nPairs, B);
}